// round 8
// baseline (speedup 1.0000x reference)
#include <cuda_runtime.h>
#include <cuda_bf16.h>
#include <cstdint>

#define BB 4
#define CC 32
#define PP 65536
#define KK 256
#define PCH 512
#define CHUNKS 2
#define CTAS_PER_BATCH 64
#define GRID (BB * CTAS_PER_BATCH)   // 256
#define THREADS 512

// smem byte layout (dynamic, relative to u32 shared base):
//   F:     [0, 65536)            pixel-major, 128 B/row, XOR-swizzled quads
//   A:     [65536, 83968)        9 planes x 2048 B
//   plist: [83968, 88064)        512 x int2 {pk, sw1}
//   cnt:   [88064, 89088)        256 ints
//   offs:  [89088, 90116)        257 ints
#define F_OFF   0u
#define A_OFF   65536u
#define PL_OFF  83968u
#define CNT_OFF 88064u
#define OFFS_OFF 89088u
#define SMEM_BYTES 90116

// [b][k][c<32]=fsum, [b][k][32]=wsum, stride 34. Zero at load; last CTA re-zeroes.
__device__ float g_fsum[BB * KK * 34];
__device__ unsigned g_done;

__device__ __forceinline__ uint32_t smem_u32(const void* p) {
    uint32_t a;
    asm("{ .reg .u64 t; cvta.to.shared.u64 t, %1; cvt.u32.u64 %0, t; }" : "=r"(a) : "l"(p));
    return a;
}
__device__ __forceinline__ float lds_f32(uint32_t a) {
    float v; asm volatile("ld.shared.f32 %0, [%1];" : "=f"(v) : "r"(a)); return v;
}
__device__ __forceinline__ int2 lds_s32x2(uint32_t a) {
    int2 v; asm volatile("ld.shared.v2.s32 {%0,%1}, [%2];" : "=r"(v.x), "=r"(v.y) : "r"(a)); return v;
}
__device__ __forceinline__ float4 lds_f32x4(uint32_t a) {
    float4 v; asm volatile("ld.shared.v4.f32 {%0,%1,%2,%3}, [%4];"
                           : "=f"(v.x), "=f"(v.y), "=f"(v.z), "=f"(v.w) : "r"(a)); return v;
}
__device__ __forceinline__ void sts_f32x4(uint32_t a, float4 v) {
    asm volatile("st.shared.v4.f32 [%0], {%1,%2,%3,%4};"
                 :: "r"(a), "f"(v.x), "f"(v.y), "f"(v.z), "f"(v.w));
}
__device__ __forceinline__ void sts_s32x2(uint32_t a, int x, int y) {
    asm volatile("st.shared.v2.s32 [%0], {%1,%2};" :: "r"(a), "r"(x), "r"(y));
}

__global__ __launch_bounds__(THREADS, 2)
void spix_main(const float* __restrict__ feats,
               const float* __restrict__ assoc,
               const int*   __restrict__ idxmap,
               float* __restrict__ out) {
    extern __shared__ float sm[];
    const uint32_t SB = smem_u32(sm);
    int* cnt  = (int*)((char*)sm + CNT_OFF);
    int* offs = (int*)((char*)sm + OFFS_OFF);

    const int b    = blockIdx.x >> 6;
    const int s    = blockIdx.x & 63;
    const int tid  = threadIdx.x;
    const int wid  = tid >> 5;
    const int lane = tid & 31;
    const int g    = lane >> 3;              // entry group 0..3
    const int cl8  = lane & 7;               // channel quad (channels 4*cl8..+3)
    const uint32_t cl16 = (uint32_t)cl8 << 4;

    if (tid < KK) cnt[tid] = 0;
    __syncthreads();

    for (int ch = 0; ch < CHUNKS; ch++) {
        const int p0 = (s * CHUNKS + ch) * PCH;

        // ---- stage F: thread = one pixel; 32 coalesced LDG.32 -> 8 STS.128 ----
        {
            const float* src = feats + (size_t)b * CC * PP + p0 + tid;
            const uint32_t row = SB + F_OFF + ((uint32_t)tid << 7);
            const uint32_t sw  = ((uint32_t)tid & 7) << 4;
#pragma unroll
            for (int cq = 0; cq < 8; cq++) {
                float4 v;
                v.x = src[(size_t)(4 * cq + 0) * PP];
                v.y = src[(size_t)(4 * cq + 1) * PP];
                v.z = src[(size_t)(4 * cq + 2) * PP];
                v.w = src[(size_t)(4 * cq + 3) * PP];
                sts_f32x4(row + ((((uint32_t)cq << 4) ^ sw) & 0x70u) + 0u, v);
            }
        }
        // ---- stage A: [j][p], 9 x 2048 B, coalesced float4 ----
        {
            const float* srcA = assoc + (size_t)b * 9 * PP + p0;
            for (int t = tid; t < 9 * PCH / 4; t += THREADS) {
                const int j  = t >> 7;
                const int q4 = (t & 127) << 2;
                float4 v = *(const float4*)(srcA + (size_t)j * PP + q4);
                sts_f32x4(SB + A_OFF + ((uint32_t)j << 11) + ((uint32_t)q4 << 2), v);
            }
        }

        // ---- count pixels per base bin ----
        const int idxA = idxmap[(size_t)b * PP + p0 + tid];
        atomicAdd(&cnt[idxA], 1);
        __syncthreads();

        // ---- exclusive scan (warp 0) ----
        if (wid == 0) {
            int running = 0;
            for (int gi = 0; gi < KK / 32; gi++) {
                const int v = cnt[gi * 32 + lane];
                int incl = v;
#pragma unroll
                for (int d = 1; d < 32; d <<= 1) {
                    int n = __shfl_up_sync(0xffffffffu, incl, d);
                    if (lane >= d) incl += n;
                }
                offs[gi * 32 + lane] = running + incl - v;
                running += __shfl_sync(0xffffffffu, incl, 31);
            }
            if (lane == 0) offs[KK] = PCH;
        }
        __syncthreads();
        if (tid < KK) cnt[tid] = offs[tid];    // cursors
        __syncthreads();

        // ---- place packed records sorted by base bin ----
        {
            const int slot = atomicAdd(&cnt[idxA], 1);
            const int pk  = ((15 - (idxA & 15)) << 11) | (tid << 2);
            const int sw1 = (tid << 7) | ((tid & 7) << 4);
            sts_s32x2(SB + PL_OFF + ((uint32_t)slot << 3), pk, sw1);
        }
        __syncthreads();
        if (tid < KK) cnt[tid] = 0;            // for next chunk

        // ---- gather: warp = target row ky=wid; 4 entries/iter via groups ----
        const uint32_t F0 = SB + F_OFF;
        const uint32_t PL = SB + PL_OFF;
        const int ky = wid;
        for (int kx = 0; kx < 16; kx++) {
            float4 acc = make_float4(0.f, 0.f, 0.f, 0.f);
            float aw = 0.f;
#pragma unroll
            for (int dy = -1; dy <= 1; dy++) {
                const int sy = ky + dy;
                if (sy < 0 || sy > 15) continue;
                const int xlo = kx > 0  ? kx - 1 : 0;
                const int xhi = kx < 15 ? kx + 1 : 15;
                const int beg = offs[sy * 16 + xlo];
                const int n   = offs[sy * 16 + xhi + 1] - beg;
                // weight plane j = 3*(1-dy) + (kx-ix+1); addr = A0 + pk always in-bounds
                const uint32_t A0 = SB + A_OFF + (uint32_t)((3 * (1 - dy) + kx - 14) << 11);
                uint32_t e8 = PL + ((uint32_t)beg << 3) + ((uint32_t)g << 3);
                for (int it = n >> 2; it > 0; --it) {
                    const int2 pr = lds_s32x2(e8);
                    e8 += 32;
                    const float  w = lds_f32(A0 + (uint32_t)pr.x);
                    const float4 f = lds_f32x4(F0 + ((uint32_t)pr.y ^ cl16));
                    acc.x += w * f.x; acc.y += w * f.y;
                    acc.z += w * f.z; acc.w += w * f.w;
                    aw += w;
                }
                if (g < (n & 3)) {
                    const int2 pr = lds_s32x2(e8);
                    const float  w = lds_f32(A0 + (uint32_t)pr.x);
                    const float4 f = lds_f32x4(F0 + ((uint32_t)pr.y ^ cl16));
                    acc.x += w * f.x; acc.y += w * f.y;
                    acc.z += w * f.z; acc.w += w * f.w;
                    aw += w;
                }
            }
            // reduce across the 4 groups (xor 8, xor 16)
#pragma unroll
            for (int d = 8; d <= 16; d <<= 1) {
                acc.x += __shfl_xor_sync(0xffffffffu, acc.x, d);
                acc.y += __shfl_xor_sync(0xffffffffu, acc.y, d);
                acc.z += __shfl_xor_sync(0xffffffffu, acc.z, d);
                acc.w += __shfl_xor_sync(0xffffffffu, acc.w, d);
                aw    += __shfl_xor_sync(0xffffffffu, aw, d);
            }
            float* gb = &g_fsum[(size_t)(b * KK + ky * 16 + kx) * 34];
            if (lane < 8) {                    // fire-and-forget REDG
                atomicAdd(gb + 4 * cl8 + 0, acc.x);
                atomicAdd(gb + 4 * cl8 + 1, acc.y);
                atomicAdd(gb + 4 * cl8 + 2, acc.z);
                atomicAdd(gb + 4 * cl8 + 3, acc.w);
            } else if (lane == 8) {
                atomicAdd(gb + 32, aw);
            }
        }
        __syncthreads();
    }

    // ---- fused epilogue: last CTA normalizes, writes out, re-zeroes scratch ----
    __shared__ unsigned s_rank;
    __threadfence();
    __syncthreads();
    if (tid == 0) s_rank = atomicAdd(&g_done, 1u);
    __syncthreads();
    if (s_rank == GRID - 1) {
        __threadfence();
        for (int i = tid; i < BB * KK * CC; i += THREADS) {
            const int c  = i & 31;
            const int bk = i >> 5;
            const float ws = g_fsum[(size_t)bk * 34 + 32];
            const float fs = g_fsum[(size_t)bk * 34 + c];
            const int k = bk & 255, bb2 = bk >> 8;
            out[((size_t)(bb2 * CC) + c) * KK + k] = (ws > 1e-16f) ? fs / ws : 0.f;
        }
        __syncthreads();
        for (int i = tid; i < BB * KK * 34; i += THREADS) g_fsum[i] = 0.f;
        if (tid == 0) g_done = 0;
    }
}

extern "C" void kernel_launch(void* const* d_in, const int* in_sizes, int n_in,
                              void* d_out, int out_size) {
    const float* feats  = (const float*)d_in[0];
    const float* assoc  = (const float*)d_in[1];
    const int*   idxmap = (const int*)d_in[2];

    static int configured = 0;
    if (!configured) {
        cudaFuncSetAttribute(spix_main, cudaFuncAttributeMaxDynamicSharedMemorySize,
                             SMEM_BYTES);
        configured = 1;
    }
    spix_main<<<GRID, THREADS, SMEM_BYTES>>>(feats, assoc, idxmap, (float*)d_out);
}